// round 5
// baseline (speedup 1.0000x reference)
#include <cuda_runtime.h>
#include <cuda_bf16.h>

// DCTExtractor: gray = 0.299R+0.587G+0.114B, per-8x8-block 2D DCT
// (D @ blk @ D^T) * mask -> (B,1,H,W).
//
// Two threads per 8x8 block (even lane: cols 0-3, odd lane: cols 4-7).
// Stage 1 (D @ blk) is column-local: acc[8][4] = 32 regs/thread.
// Halves exchanged through padded smem (same warp -> __syncwarp only).
// Stage 2 reads 4 rows back, applies D^T + mask, writes full rows.
// ~70 regs/thread -> 3 CTAs/SM (24 warps) vs 16 before: latency-bound fix.

#define TPB 256
#define BPC 128            // blocks per CTA (TPB/2)
#define CSTRIDE 72         // floats per block in smem (8x8 + 8 pad)

__global__ __launch_bounds__(TPB, 3)
void dct_extract_kernel(const float* __restrict__ x,
                        const float* __restrict__ dctm,
                        const float* __restrict__ mask,
                        float* __restrict__ out,
                        int total)
{
    __shared__ float Ds[64];
    __shared__ float Ms[64];
    __shared__ float Cs[BPC * CSTRIDE];   // 36864 B

    const int t = threadIdx.x;
    if (t < 64)       Ds[t]      = dctm[t];
    else if (t < 128) Ms[t - 64] = mask[t - 64];
    __syncthreads();

    const int W  = 512;
    const int HW = 512 * 512;

    const int blk_local = t >> 1;                 // 0..127
    const int half      = t & 1;                  // 0: cols 0-3, 1: cols 4-7
    const int gid       = blockIdx.x * BPC + blk_local;
    const bool active   = (gid < total);

    int b = 0, by = 0, bx = 0;
    if (active) {
        b  = gid >> 12;          // 4096 blocks per image (64x64)
        const int rr = gid & 4095;
        by = rr >> 6;
        bx = rr & 63;
    }

    // ---------------- stage 1: acc = D @ gray_block (my 4 columns) ----------------
    if (active) {
        const float* p0 = x + (size_t)b * 3 * HW + (size_t)(by * 8) * W
                            + bx * 8 + half * 4;
        float acc[8][4];
#pragma unroll
        for (int j = 0; j < 8; ++j) {
            const float* row = p0 + j * W;
            const float4 rc = __ldcs((const float4*)(row));
            const float4 gc = __ldcs((const float4*)(row + HW));
            const float4 bc = __ldcs((const float4*)(row + 2 * HW));
            float grow[4];
            grow[0] = fmaf(0.114f, bc.x, fmaf(0.587f, gc.x, 0.299f * rc.x));
            grow[1] = fmaf(0.114f, bc.y, fmaf(0.587f, gc.y, 0.299f * rc.y));
            grow[2] = fmaf(0.114f, bc.z, fmaf(0.587f, gc.z, 0.299f * rc.z));
            grow[3] = fmaf(0.114f, bc.w, fmaf(0.587f, gc.w, 0.299f * rc.w));
#pragma unroll
            for (int i = 0; i < 8; ++i) {
                const float dij = Ds[i * 8 + j];   // uniform broadcast
                if (j == 0) {
#pragma unroll
                    for (int k = 0; k < 4; ++k) acc[i][k] = dij * grow[k];
                } else {
#pragma unroll
                    for (int k = 0; k < 4; ++k) acc[i][k] = fmaf(dij, grow[k], acc[i][k]);
                }
            }
        }
        // stash my column half: Cs[blk][i*8 + half*4 .. +3]
        float* cb = Cs + blk_local * CSTRIDE + half * 4;
#pragma unroll
        for (int i = 0; i < 8; ++i)
            *(float4*)(cb + i * 8) = make_float4(acc[i][0], acc[i][1], acc[i][2], acc[i][3]);
    }

    __syncwarp();   // both halves of each block live in the same warp

    // ---------------- stage 2: out rows = (acc @ D^T) * mask (my 4 rows) ----------------
    if (active) {
        const float* cr = Cs + blk_local * CSTRIDE;
        float* po = out + (size_t)b * HW + (size_t)(by * 8) * W + bx * 8;
#pragma unroll
        for (int ii = 0; ii < 4; ++ii) {
            const int i = half * 4 + ii;
            const float4 c0 = *(const float4*)(cr + i * 8);
            const float4 c1 = *(const float4*)(cr + i * 8 + 4);
            const float c[8] = { c0.x, c0.y, c0.z, c0.w, c1.x, c1.y, c1.z, c1.w };
            float o[8];
#pragma unroll
            for (int l = 0; l < 8; ++l) {
                float s = c[0] * Ds[l * 8 + 0];
#pragma unroll
                for (int k = 1; k < 8; ++k)
                    s = fmaf(c[k], Ds[l * 8 + k], s);
                o[l] = s * Ms[i * 8 + l];
            }
            float* row = po + i * W;
            __stcs((float4*)(row),     make_float4(o[0], o[1], o[2], o[3]));
            __stcs((float4*)(row + 4), make_float4(o[4], o[5], o[6], o[7]));
        }
    }
}

extern "C" void kernel_launch(void* const* d_in, const int* in_sizes, int n_in,
                              void* d_out, int out_size)
{
    const float* x    = (const float*)d_in[0];
    const float* dctm = (const float*)d_in[1];
    const float* mask = (const float*)d_in[2];
    float* out        = (float*)d_out;

    const int HW = 512 * 512;
    const int B  = in_sizes[0] / (3 * HW);      // 64
    const int total = B * 64 * 64;              // 8x8 blocks; 2 threads each

    const int grid = (total + BPC - 1) / BPC;   // 2048 for B=64
    dct_extract_kernel<<<grid, TPB>>>(x, dctm, mask, out, total);
}